// round 2
// baseline (speedup 1.0000x reference)
#include <cuda_runtime.h>
#include <cuda_fp16.h>
#include <cstdint>

// ============================================================================
// out[M,N] = X[M,K] @ Wq[N,K]^T ;  M=4096, N=4096, K=4096, GROUP=128
// Plain sm_100 target: no tcgen05 / no TMA. Use mma.sync (HMMA) + cp.async.
// ============================================================================
#define MDIM 4096
#define NDIM 4096
#define KDIM 4096

#define BM 128
#define BN 256
#define BK 64          // 64 halves = 128B rows -> SW128 swizzle atom
#define STAGES 3

#define A_BYTES (BM * 128)                 // 16 KB
#define B_BYTES (BN * 128)                 // 32 KB
#define STAGE_BYTES (A_BYTES + B_BYTES)    // 48 KB
#define SMEM_TOTAL (STAGES * STAGE_BYTES)  // 144 KB

// ============================================================================
// Scratch (__device__ globals: allocation-free rule)
// ============================================================================
__device__ __half g_xh[(size_t)MDIM * KDIM];   // 32 MB
__device__ __half g_wh[(size_t)NDIM * KDIM];   // 32 MB

// ============================================================================
// Helpers
// ============================================================================
__device__ __forceinline__ uint32_t smem_u32(const void* p) {
    uint32_t a;
    asm("{ .reg .u64 t; cvta.to.shared.u64 t, %1; cvt.u32.u64 %0, t; }"
        : "=r"(a) : "l"(p));
    return a;
}

#define SWZ(off) ((off) ^ (((off) >> 3) & 0x70))

#define CP_ASYNC_16(smem_addr, gptr) \
    asm volatile("cp.async.cg.shared.global [%0], [%1], 16;" \
        :: "r"(smem_addr), "l"(gptr))

#define CP_COMMIT() asm volatile("cp.async.commit_group;" ::: "memory")
#define CP_WAIT1()  asm volatile("cp.async.wait_group 1;" ::: "memory")

__device__ __forceinline__ void ldsm_x4(uint32_t& r0, uint32_t& r1,
                                        uint32_t& r2, uint32_t& r3,
                                        uint32_t addr) {
    asm volatile("ldmatrix.sync.aligned.m8n8.x4.shared.b16 {%0,%1,%2,%3}, [%4];"
        : "=r"(r0), "=r"(r1), "=r"(r2), "=r"(r3) : "r"(addr));
}

__device__ __forceinline__ void mma16816(float* c, const uint32_t* a,
                                         uint32_t b0, uint32_t b1) {
    asm volatile(
        "mma.sync.aligned.m16n8k16.row.col.f32.f16.f16.f32 "
        "{%0,%1,%2,%3}, {%4,%5,%6,%7}, {%8,%9}, {%0,%1,%2,%3};"
        : "+f"(c[0]), "+f"(c[1]), "+f"(c[2]), "+f"(c[3])
        : "r"(a[0]), "r"(a[1]), "r"(a[2]), "r"(a[3]), "r"(b0), "r"(b1));
}

// ============================================================================
// Kernel 1: x f32 -> f16
// ============================================================================
__global__ void __launch_bounds__(256) cvt_x_kernel(const float4* __restrict__ x,
                                                    uint2* __restrict__ xh) {
    int i = blockIdx.x * 256 + threadIdx.x;
    float4 v = x[i];
    __half2 a = __floats2half2_rn(v.x, v.y);
    __half2 b = __floats2half2_rn(v.z, v.w);
    uint2 u;
    u.x = *reinterpret_cast<uint32_t*>(&a);
    u.y = *reinterpret_cast<uint32_t*>(&b);
    xh[i] = u;
}

// ============================================================================
// Kernel 2: ternary group-quantize weight -> f16 {-scale, 0, +scale}
// One warp per 128-elem group (lane owns 4 consecutive floats).
// ============================================================================
__global__ void __launch_bounds__(256) quantize_w_kernel(const float4* __restrict__ w,
                                                         uint2* __restrict__ wh) {
    int gwarp = (blockIdx.x * 256 + threadIdx.x) >> 5;
    int lane = threadIdx.x & 31;
    size_t idx = (size_t)gwarp * 32 + lane;
    float4 v = w[idx];
    float s = fabsf(v.x) + fabsf(v.y) + fabsf(v.z) + fabsf(v.w);
    #pragma unroll
    for (int o = 16; o; o >>= 1) s += __shfl_xor_sync(0xFFFFFFFFu, s, o);
    float scale = fmaxf(s * (1.0f / 128.0f), 1e-8f);
    float thr = 0.5f * scale;
    __half hp = __float2half_rn(scale);
    __half hn = __hneg(hp);
    __half hz = __float2half_rn(0.0f);
    __half q[4];
    q[0] = v.x > thr ? hp : (v.x < -thr ? hn : hz);
    q[1] = v.y > thr ? hp : (v.y < -thr ? hn : hz);
    q[2] = v.z > thr ? hp : (v.z < -thr ? hn : hz);
    q[3] = v.w > thr ? hp : (v.w < -thr ? hn : hz);
    wh[idx] = *reinterpret_cast<uint2*>(q);
}

// ============================================================================
// Kernel 3: HMMA GEMM. CTA 128x256x64, 3-stage cp.async, warp tile 64x64.
//   A = g_xh [M,K] row-major, B = g_wh [N,K] row-major, D = A @ B^T (f32).
// ============================================================================
__global__ void __launch_bounds__(256, 1) gemm_f16_kernel(
    const __half* __restrict__ A,
    const __half* __restrict__ B,
    float* __restrict__ C
) {
    extern __shared__ char smem[];
    const uint32_t sbase = smem_u32(smem);
    const int tid = threadIdx.x;
    const int wid = tid >> 5;
    const int lane = tid & 31;
    const int wm = wid >> 2;        // 0..1  (m warp)
    const int wn = wid & 3;         // 0..3  (n warp)
    const int m0 = blockIdx.y * BM;
    const int n0 = blockIdx.x * BN;

    const uint4* Ag = reinterpret_cast<const uint4*>(A) + (size_t)m0 * (KDIM / 8);
    const uint4* Bg = reinterpret_cast<const uint4*>(B) + (size_t)n0 * (KDIM / 8);

    // cp.async indexing: idx -> (row, 16B-seg)
    const int ldrowA = tid >> 3, ldseg = tid & 7;          // A: 4 iters of 256
    const int ldrowB = tid >> 3;                           // B: 8 iters of 256

    auto load_stage = [&](int kt, int s) {
        const uint32_t sA = sbase + s * STAGE_BYTES;
        const uint32_t sB = sA + A_BYTES;
        const size_t kseg = (size_t)kt * (BK / 8) + ldseg;
        #pragma unroll
        for (int i = 0; i < 4; i++) {
            int row = ldrowA + i * 32;
            uint32_t off = SWZ((uint32_t)(row * 128 + ldseg * 16));
            CP_ASYNC_16(sA + off, Ag + (size_t)row * (KDIM / 8) + kseg);
        }
        #pragma unroll
        for (int i = 0; i < 8; i++) {
            int row = ldrowB + i * 32;
            uint32_t off = SWZ((uint32_t)(row * 128 + ldseg * 16));
            CP_ASYNC_16(sB + off, Bg + (size_t)row * (KDIM / 8) + kseg);
        }
    };

    // Prologue: stages 0,1
    load_stage(0, 0); CP_COMMIT();
    load_stage(1, 1); CP_COMMIT();

    float c[4][8][4];
    #pragma unroll
    for (int i = 0; i < 4; i++)
        #pragma unroll
        for (int j = 0; j < 8; j++)
            #pragma unroll
            for (int t = 0; t < 4; t++) c[i][j][t] = 0.0f;

    // ldmatrix base addressing (row = lane%16, 16B col select = lane/16)
    const int lrow = lane & 15;
    const int lcolb = (lane >> 4) * 16;
    const uint32_t aRow = (uint32_t)(wm * 64 + lrow);
    const uint32_t bRow = (uint32_t)(wn * 64 + lrow);

    const int KT = KDIM / BK;   // 64

    for (int kt = 0; kt < KT; kt++) {
        const int s = kt % STAGES;
        CP_WAIT1();
        __syncthreads();

        // Prefetch stage kt+2 into buffer freed last iteration
        if (kt + 2 < KT) load_stage(kt + 2, (kt + 2) % STAGES);
        CP_COMMIT();

        const uint32_t sA = sbase + s * STAGE_BYTES;
        const uint32_t sB = sA + A_BYTES;

        #pragma unroll
        for (int ks = 0; ks < 4; ks++) {
            const int colb = ks * 32 + lcolb;
            uint32_t a[4][4];
            uint32_t b[8][2];
            #pragma unroll
            for (int i = 0; i < 4; i++) {
                uint32_t off = SWZ((uint32_t)((aRow + i * 16) * 128 + colb));
                ldsm_x4(a[i][0], a[i][1], a[i][2], a[i][3], sA + off);
            }
            #pragma unroll
            for (int j = 0; j < 4; j++) {
                uint32_t r0, r1, r2, r3;
                uint32_t off = SWZ((uint32_t)((bRow + j * 16) * 128 + colb));
                ldsm_x4(r0, r1, r2, r3, sB + off);
                b[2 * j][0] = r0; b[2 * j][1] = r2;
                b[2 * j + 1][0] = r1; b[2 * j + 1][1] = r3;
            }
            #pragma unroll
            for (int i = 0; i < 4; i++)
                #pragma unroll
                for (int j = 0; j < 8; j++)
                    mma16816(c[i][j], a[i], b[j][0], b[j][1]);
        }
        __syncthreads();
    }

    // Epilogue: direct f32 stores (float2 per mma tile row; 32B sectors OK)
    const int erow = (lane >> 2);
    const int ecol = 2 * (lane & 3);
    #pragma unroll
    for (int i = 0; i < 4; i++) {
        const int row = m0 + wm * 64 + i * 16 + erow;
        float* out0 = C + (size_t)row * NDIM + n0 + wn * 64 + ecol;
        float* out1 = out0 + 8 * NDIM;
        #pragma unroll
        for (int j = 0; j < 8; j++) {
            *reinterpret_cast<float2*>(out0 + j * 8) = make_float2(c[i][j][0], c[i][j][1]);
            *reinterpret_cast<float2*>(out1 + j * 8) = make_float2(c[i][j][2], c[i][j][3]);
        }
    }
}

// ============================================================================
// kernel_launch
// ============================================================================
extern "C" void kernel_launch(void* const* d_in, const int* in_sizes, int n_in,
                              void* d_out, int out_size) {
    (void)in_sizes; (void)n_in; (void)out_size;
    const float* x = (const float*)d_in[0];       // [2,2048,4096] f32
    const float* w = (const float*)d_in[1];       // [4096,4096] f32
    float* out = (float*)d_out;                   // [2,2048,4096] f32

    void* xh_p = nullptr;
    void* wh_p = nullptr;
    cudaGetSymbolAddress(&xh_p, g_xh);
    cudaGetSymbolAddress(&wh_p, g_wh);

    cvt_x_kernel<<<16384, 256>>>((const float4*)x, (uint2*)xh_p);
    quantize_w_kernel<<<16384, 256>>>((const float4*)w, (uint2*)wh_p);

    cudaFuncSetAttribute(gemm_f16_kernel,
                         cudaFuncAttributeMaxDynamicSharedMemorySize, SMEM_TOTAL);
    dim3 grid(NDIM / BN, MDIM / BM);   // (16, 32)
    gemm_f16_kernel<<<grid, 256, SMEM_TOTAL>>>((const __half*)xh_p,
                                               (const __half*)wh_p, out);
}

// round 4
// speedup vs baseline: 1.0252x; 1.0252x over previous
#include <cuda_runtime.h>
#include <cuda_fp16.h>
#include <cstdint>

// ============================================================================
// out[M,N] = X[M,K] @ Wq[N,K]^T ;  M=4096, N=4096, K=4096, GROUP=128
// Plain sm_100 target: mma.sync (HMMA) + cp.async. No tcgen05/TMA ('a'-gated).
// ============================================================================
#define MDIM 4096
#define NDIM 4096
#define KDIM 4096

#define BM 128
#define BN 256
#define BK 64          // 64 halves = 128B rows -> SW128 swizzle atom
#define STAGES 3

#define A_BYTES (BM * 128)                 // 16 KB
#define B_BYTES (BN * 128)                 // 32 KB
#define STAGE_BYTES (A_BYTES + B_BYTES)    // 48 KB
#define SMEM_TOTAL (STAGES * STAGE_BYTES)  // 144 KB

// ============================================================================
// Scratch (__device__ globals: allocation-free rule)
// ============================================================================
__device__ __half g_xh[(size_t)MDIM * KDIM];   // 32 MB
__device__ __half g_wh[(size_t)NDIM * KDIM];   // 32 MB

// ============================================================================
// Helpers
// ============================================================================
__device__ __forceinline__ uint32_t smem_u32(const void* p) {
    uint32_t a;
    asm("{ .reg .u64 t; cvta.to.shared.u64 t, %1; cvt.u32.u64 %0, t; }"
        : "=r"(a) : "l"(p));
    return a;
}

#define SWZ(off) ((off) ^ (((off) >> 3) & 0x70))

#define CP_ASYNC_16(smem_addr, gptr) \
    asm volatile("cp.async.cg.shared.global [%0], [%1], 16;" \
        :: "r"(smem_addr), "l"(gptr))

#define CP_COMMIT() asm volatile("cp.async.commit_group;" ::: "memory")
#define CP_WAIT1()  asm volatile("cp.async.wait_group 1;" ::: "memory")

__device__ __forceinline__ void ldsm_x4(uint32_t& r0, uint32_t& r1,
                                        uint32_t& r2, uint32_t& r3,
                                        uint32_t addr) {
    asm volatile("ldmatrix.sync.aligned.m8n8.x4.shared.b16 {%0,%1,%2,%3}, [%4];"
        : "=r"(r0), "=r"(r1), "=r"(r2), "=r"(r3) : "r"(addr));
}

__device__ __forceinline__ void mma16816(float* c, const uint32_t* a,
                                         uint32_t b0, uint32_t b1) {
    asm volatile(
        "mma.sync.aligned.m16n8k16.row.col.f32.f16.f16.f32 "
        "{%0,%1,%2,%3}, {%4,%5,%6,%7}, {%8,%9}, {%0,%1,%2,%3};"
        : "+f"(c[0]), "+f"(c[1]), "+f"(c[2]), "+f"(c[3])
        : "r"(a[0]), "r"(a[1]), "r"(a[2]), "r"(a[3]), "r"(b0), "r"(b1));
}

// ============================================================================
// Kernel 1: x f32 -> f16 (2x float4 in, 1x uint4 out per thread)
// ============================================================================
__global__ void __launch_bounds__(256) cvt_x_kernel(const float4* __restrict__ x,
                                                    uint4* __restrict__ xh) {
    int i = blockIdx.x * 256 + threadIdx.x;
    float4 v0 = x[2 * i];
    float4 v1 = x[2 * i + 1];
    __half2 a = __floats2half2_rn(v0.x, v0.y);
    __half2 b = __floats2half2_rn(v0.z, v0.w);
    __half2 c = __floats2half2_rn(v1.x, v1.y);
    __half2 d = __floats2half2_rn(v1.z, v1.w);
    uint4 u;
    u.x = *reinterpret_cast<uint32_t*>(&a);
    u.y = *reinterpret_cast<uint32_t*>(&b);
    u.z = *reinterpret_cast<uint32_t*>(&c);
    u.w = *reinterpret_cast<uint32_t*>(&d);
    xh[i] = u;
}

// ============================================================================
// Kernel 2: ternary group-quantize weight -> f16 {-scale, 0, +scale}
// Half-warp (16 lanes) per 128-elem group; 8 elems per lane.
// A group = 128 floats = 32 float4 (input units) = 16 uint4-of-8-halves (output).
// ============================================================================
__global__ void __launch_bounds__(256) quantize_w_kernel(const float4* __restrict__ w,
                                                         uint4* __restrict__ wh) {
    int gwarp = (blockIdx.x * 256 + threadIdx.x) >> 5;
    int lane = threadIdx.x & 31;
    int hw = lane >> 4;                  // half-warp -> which group
    int hl = lane & 15;                  // lane within group
    size_t group = (size_t)gwarp * 2 + hw;
    size_t f4base = group * 32 + hl * 2; // FIX: 32 float4 per 128-elem group
    float4 v0 = w[f4base];
    float4 v1 = w[f4base + 1];
    float s = fabsf(v0.x) + fabsf(v0.y) + fabsf(v0.z) + fabsf(v0.w)
            + fabsf(v1.x) + fabsf(v1.y) + fabsf(v1.z) + fabsf(v1.w);
    #pragma unroll
    for (int o = 8; o; o >>= 1) s += __shfl_xor_sync(0xFFFFFFFFu, s, o, 16);
    float scale = fmaxf(s * (1.0f / 128.0f), 1e-8f);
    float thr = 0.5f * scale;
    __half hp = __float2half_rn(scale);
    __half hn = __hneg(hp);
    __half hz = __float2half_rn(0.0f);
    __half q[8];
    float f[8] = {v0.x, v0.y, v0.z, v0.w, v1.x, v1.y, v1.z, v1.w};
    #pragma unroll
    for (int j = 0; j < 8; j++)
        q[j] = f[j] > thr ? hp : (f[j] < -thr ? hn : hz);
    wh[group * 16 + hl] = *reinterpret_cast<uint4*>(q);
}

// ============================================================================
// Kernel 3: HMMA GEMM. CTA 128x256x64, 3-stage cp.async, warp tile 64x64.
// Fragment double-buffering across ks; single syncthreads per k-tile.
// ============================================================================
__global__ void __launch_bounds__(256, 1) gemm_f16_kernel(
    const __half* __restrict__ A,
    const __half* __restrict__ B,
    float* __restrict__ C
) {
    extern __shared__ char smem[];
    const uint32_t sbase = smem_u32(smem);
    const int tid = threadIdx.x;
    const int wid = tid >> 5;
    const int lane = tid & 31;
    const int wm = wid >> 2;        // 0..1
    const int wn = wid & 3;         // 0..3
    const int m0 = blockIdx.y * BM;
    const int n0 = blockIdx.x * BN;

    const uint4* Ag = reinterpret_cast<const uint4*>(A) + (size_t)m0 * (KDIM / 8);
    const uint4* Bg = reinterpret_cast<const uint4*>(B) + (size_t)n0 * (KDIM / 8);

    const int ldrow = tid >> 3, ldseg = tid & 7;

    auto load_stage = [&](int kt, int s) {
        const uint32_t sA = sbase + s * STAGE_BYTES;
        const uint32_t sB = sA + A_BYTES;
        const size_t kseg = (size_t)kt * (BK / 8) + ldseg;
        #pragma unroll
        for (int i = 0; i < 4; i++) {
            int row = ldrow + i * 32;
            uint32_t off = SWZ((uint32_t)(row * 128 + ldseg * 16));
            CP_ASYNC_16(sA + off, Ag + (size_t)row * (KDIM / 8) + kseg);
        }
        #pragma unroll
        for (int i = 0; i < 8; i++) {
            int row = ldrow + i * 32;
            uint32_t off = SWZ((uint32_t)(row * 128 + ldseg * 16));
            CP_ASYNC_16(sB + off, Bg + (size_t)row * (KDIM / 8) + kseg);
        }
    };

    load_stage(0, 0); CP_COMMIT();
    load_stage(1, 1); CP_COMMIT();

    float c[4][8][4];
    #pragma unroll
    for (int i = 0; i < 4; i++)
        #pragma unroll
        for (int j = 0; j < 8; j++)
            #pragma unroll
            for (int t = 0; t < 4; t++) c[i][j][t] = 0.0f;

    const int lrow = lane & 15;
    const int lcolb = (lane >> 4) * 16;
    const uint32_t aRow = (uint32_t)(wm * 64 + lrow);
    const uint32_t bRow = (uint32_t)(wn * 64 + lrow);

    uint32_t af[2][4][4];
    uint32_t bf[2][8][2];

    auto load_frags = [&](uint32_t sA, uint32_t sB, int ks, int buf) {
        const int colb = ks * 32 + lcolb;
        #pragma unroll
        for (int i = 0; i < 4; i++) {
            uint32_t off = SWZ((uint32_t)((aRow + i * 16) * 128 + colb));
            ldsm_x4(af[buf][i][0], af[buf][i][1], af[buf][i][2], af[buf][i][3],
                    sA + off);
        }
        #pragma unroll
        for (int j = 0; j < 4; j++) {
            uint32_t r0, r1, r2, r3;
            uint32_t off = SWZ((uint32_t)((bRow + j * 16) * 128 + colb));
            ldsm_x4(r0, r1, r2, r3, sB + off);
            bf[buf][2 * j][0] = r0; bf[buf][2 * j][1] = r2;
            bf[buf][2 * j + 1][0] = r1; bf[buf][2 * j + 1][1] = r3;
        }
    };

    const int KT = KDIM / BK;   // 64

    for (int kt = 0; kt < KT; kt++) {
        const int s = kt % STAGES;
        CP_WAIT1();
        __syncthreads();
        // All warps passed the barrier => all finished consuming the buffer
        // the prefetch below overwrites (they consumed it in iteration kt-1).
        if (kt + 2 < KT) load_stage(kt + 2, (kt + 2) % STAGES);
        CP_COMMIT();

        const uint32_t sA = sbase + s * STAGE_BYTES;
        const uint32_t sB = sA + A_BYTES;

        load_frags(sA, sB, 0, 0);
        #pragma unroll
        for (int ks = 0; ks < 4; ks++) {
            const int cur = ks & 1;
            if (ks < 3) load_frags(sA, sB, ks + 1, cur ^ 1);
            #pragma unroll
            for (int i = 0; i < 4; i++)
                #pragma unroll
                for (int j = 0; j < 8; j++)
                    mma16816(c[i][j], af[cur][i], bf[cur][j][0], bf[cur][j][1]);
        }
        // No trailing syncthreads: leading barrier of next iteration protects
        // the buffer that iteration's prefetch overwrites.
    }

    // Epilogue
    const int erow = (lane >> 2);
    const int ecol = 2 * (lane & 3);
    #pragma unroll
    for (int i = 0; i < 4; i++) {
        const int row = m0 + wm * 64 + i * 16 + erow;
        float* out0 = C + (size_t)row * NDIM + n0 + wn * 64 + ecol;
        float* out1 = out0 + 8 * NDIM;
        #pragma unroll
        for (int j = 0; j < 8; j++) {
            *reinterpret_cast<float2*>(out0 + j * 8) = make_float2(c[i][j][0], c[i][j][1]);
            *reinterpret_cast<float2*>(out1 + j * 8) = make_float2(c[i][j][2], c[i][j][3]);
        }
    }
}

// ============================================================================
// kernel_launch
// ============================================================================
extern "C" void kernel_launch(void* const* d_in, const int* in_sizes, int n_in,
                              void* d_out, int out_size) {
    (void)in_sizes; (void)n_in; (void)out_size;
    const float* x = (const float*)d_in[0];       // [2,2048,4096] f32
    const float* w = (const float*)d_in[1];       // [4096,4096] f32
    float* out = (float*)d_out;                   // [2,2048,4096] f32

    void* xh_p = nullptr;
    void* wh_p = nullptr;
    cudaGetSymbolAddress(&xh_p, g_xh);
    cudaGetSymbolAddress(&wh_p, g_wh);

    // x: 16777216 elems / 8 per thread = 2097152 threads = 8192 blocks
    cvt_x_kernel<<<8192, 256>>>((const float4*)x, (uint4*)xh_p);
    // 131072 groups, 2 per warp, 8 warps/block -> 8192 blocks
    quantize_w_kernel<<<8192, 256>>>((const float4*)w, (uint4*)wh_p);

    cudaFuncSetAttribute(gemm_f16_kernel,
                         cudaFuncAttributeMaxDynamicSharedMemorySize, SMEM_TOTAL);
    dim3 grid(NDIM / BN, MDIM / BM);   // (16, 32)
    gemm_f16_kernel<<<grid, 256, SMEM_TOTAL>>>((const __half*)xh_p,
                                               (const __half*)wh_p, out);
}